// round 13
// baseline (speedup 1.0000x reference)
#include <cuda_runtime.h>
#include <cuda_bf16.h>
#include <math.h>
#include <stdint.h>

#define B_   32
#define NN   511
#define F_   512
#define NP   255
#define NC   2048   // fe fused output width: [iou(1536) | f(512)]
#define KS   1024   // split activation width: [hi(512) | lo(512)]
#define LVLF_OFF ((size_t)8 * 1024 * 1024)   // float offset of f-region inside g_lvl

// ---------------- scratch (static device memory) ----------------
__device__ __align__(16) float g_enode [B_*F_];
__device__ __align__(16) float g_eforw [B_*F_];
__device__ __align__(16) float g_logits[B_*NN];
__device__ __align__(16) float g_h     [B_*NN*F_];
__device__ __align__(16) float g_c     [B_*NN*F_];
__device__ __align__(16) float g_feiou [(size_t)B_*NN*NC];
__device__ __align__(16) float g_lvl   [(size_t)B_*256*NC];   // iou slices | f slices
__device__ __align__(16) __nv_bfloat16 g_f2s   [(size_t)B_*NN*KS];
__device__ __align__(16) __nv_bfloat16 g_hsplit[(size_t)B_*NN*KS];
__device__ __align__(16) __nv_bfloat16 g_hsum  [(size_t)B_*128*KS];  // pair-sum split
__device__ __align__(16) __nv_bfloat16 g_wfe   [(size_t)NC*KS];
__device__ __align__(16) __nv_bfloat16 g_wu    [(size_t)NC*KS];
__device__ __align__(16) float g_biascat[NC];

__device__ __forceinline__ float sigm(float x) { return 1.f / (1.f + expf(-x)); }
__device__ __forceinline__ uint32_t smem_u32(const void* p) {
    uint32_t a;
    asm("{ .reg .u64 t; cvta.to.shared.u64 t, %1; cvt.u32.u64 %0, t; }" : "=r"(a) : "l"(p));
    return a;
}
#define SWZ(o) ((o) ^ (((o) >> 3) & 0x70))
#define CP16(d, s) asm volatile("cp.async.cg.shared.global [%0], [%1], 16;" :: "r"(d), "l"(s))
#define CP_COMMIT() asm volatile("cp.async.commit_group;")
#define CP_WAIT(n)  asm volatile("cp.async.wait_group %0;" :: "n"(n))

__device__ __forceinline__ void ldmx4(uint32_t* r, uint32_t addr) {
    asm volatile("ldmatrix.sync.aligned.m8n8.x4.shared.b16 {%0,%1,%2,%3}, [%4];"
                 : "=r"(r[0]), "=r"(r[1]), "=r"(r[2]), "=r"(r[3]) : "r"(addr));
}
__device__ __forceinline__ void ldmx2(uint32_t* r, uint32_t addr) {
    asm volatile("ldmatrix.sync.aligned.m8n8.x2.shared.b16 {%0,%1}, [%2];"
                 : "=r"(r[0]), "=r"(r[1]) : "r"(addr));
}
__device__ __forceinline__ void mma16816(float* d, const uint32_t* a, const uint32_t* b) {
    asm volatile("mma.sync.aligned.m16n8k16.row.col.f32.bf16.bf16.f32 "
                 "{%0,%1,%2,%3}, {%4,%5,%6,%7}, {%8,%9}, {%0,%1,%2,%3};"
                 : "+f"(d[0]), "+f"(d[1]), "+f"(d[2]), "+f"(d[3])
                 : "r"(a[0]), "r"(a[1]), "r"(a[2]), "r"(a[3]), "r"(b[0]), "r"(b[1]));
}
__device__ __forceinline__ void add4(float4& a, float4 b) {
    a.x += b.x; a.y += b.y; a.z += b.z; a.w += b.w;
}

// ================= all weights split in ONE launch ================
__global__ void wsplit_all(const float* __restrict__ Wfeiou, const float* __restrict__ Wfef,
                           const float* __restrict__ Wuiou,  const float* __restrict__ Wuf,
                           __nv_bfloat16* __restrict__ Ofe, __nv_bfloat16* __restrict__ Ou,
                           const float* __restrict__ b_iou, const float* __restrict__ b_f,
                           float* __restrict__ bias) {
    int idx = blockIdx.x * blockDim.x + threadIdx.x;
    if (idx < NC) bias[idx] = (idx < 1536) ? b_iou[idx] : b_f[idx - 1536];
    if (idx >= 2 * NC * 512) return;
    int which = idx >= NC * 512;
    int rem = which ? idx - NC * 512 : idx;
    int r = rem >> 9, k = rem & 511;
    const float* W = which ? (r < 1536 ? Wuiou : Wuf) : (r < 1536 ? Wfeiou : Wfef);
    int rl = (r < 1536) ? r : r - 1536;
    float v = W[(size_t)rl * 512 + k];
    __nv_bfloat16 hi = __float2bfloat16_rn(v);
    __nv_bfloat16 lo = __float2bfloat16_rn(v - __bfloat162float(hi));
    __nv_bfloat16* O = which ? Ou : Ofe;
    O[(size_t)r * KS + k]       = hi;
    O[(size_t)r * KS + 512 + k] = lo;
}

// ================= bf16 HMMA dual-GEMM: blockIdx.x range selects GP ===========
// A gather: b = m / rows, node = base + m % rows, srcA = As + (b*NN+node)*KS.
//   (compact A: set rows = M, base = 0.)
// Output: row = outScatter ? (b*NN+node) : m, stride ncols; split-K slice z at C + z*M*ncols.
struct GP {
    const __nv_bfloat16* As; const __nv_bfloat16* Wc; const float* bias; float* C;
    int M, rows, base, outScatter, gx, ncols;
};

#define TILE_BYTES 16384
#define NSTAGE 3
#define GSMEM (NSTAGE * 2 * TILE_BYTES + 1024)

__global__ void __launch_bounds__(256) dual_gemm(GP g0, GP g1) {
    extern __shared__ char smem_dyn[];
    const bool first = ((int)blockIdx.x < g0.gx);
    const GP& g = first ? g0 : g1;
    const int xo = first ? blockIdx.x : blockIdx.x - g0.gx;
    if (xo >= g.gx) return;
    const int tileN = xo * 128;
    const int tileM = blockIdx.y * 128;
    if (tileM >= g.M) return;

    const uint32_t sb0 = smem_u32(smem_dyn);
    const uint32_t ab  = (sb0 + 1023u) & ~1023u;
    const int tid = threadIdx.x;
    const int wid = tid >> 5, lane = tid & 31;
    const int mw = (wid & 1) * 64;
    const int nw = (wid >> 1) * 32;

    const int row  = tid >> 1;
    const int c16b = (tid & 1) * 4;
    int row_g = tileM + row; if (row_g >= g.M) row_g = g.M - 1;
    int b = row_g / g.rows, node = g.base + row_g % g.rows;
    const __nv_bfloat16* srcA = g.As + (size_t)(b * NN + node) * KS;
    const __nv_bfloat16* srcB = g.Wc + (size_t)(tileN + row) * KS;

    const int gz = gridDim.z;
    const int nt = 24 / gz;
    const int kBase = blockIdx.z * nt;

    auto issue = [&](int c, int buf) {
        const int segsel = c >> 3;
        const int aseg = (segsel == 1) ? 512 : 0;
        const int bseg = (segsel == 2) ? 512 : 0;
        const int kb = (c & 7) * 64;
        const uint32_t sA = ab + buf * 2 * TILE_BYTES;
        const uint32_t sB = sA + TILE_BYTES;
        #pragma unroll
        for (int s = 0; s < 4; s++) {
            int cs = c16b + s;
            int eo = kb + cs * 8;
            CP16(sA + SWZ(row * 128 + cs * 16), srcA + aseg + eo);
            CP16(sB + SWZ(row * 128 + cs * 16), srcB + bseg + eo);
        }
        CP_COMMIT();
    };

    float acc[4][4][4] = {};
    const int a_r = lane & 15, a_q = (lane >> 4) * 16;
    const int b_r = lane & 7,  b_q = ((lane >> 3) & 1) * 16;

    issue(kBase + 0, 0);
    issue(kBase + 1, 1);
    for (int t = 0; t < nt; t++) {
        if (t + 1 < nt) CP_WAIT(1); else CP_WAIT(0);
        __syncthreads();
        const uint32_t sAb = ab + (t % NSTAGE) * 2 * TILE_BYTES;
        const uint32_t sBb = sAb + TILE_BYTES;
        #pragma unroll
        for (int ks = 0; ks < 4; ks++) {
            uint32_t af[4][4], bf[4][2];
            #pragma unroll
            for (int mi = 0; mi < 4; mi++)
                ldmx4(af[mi], sAb + SWZ((mw + mi * 16 + a_r) * 128 + ks * 32 + a_q));
            #pragma unroll
            for (int ni = 0; ni < 4; ni++)
                ldmx2(bf[ni], sBb + SWZ((nw + ni * 8 + b_r) * 128 + ks * 32 + b_q));
            #pragma unroll
            for (int mi = 0; mi < 4; mi++)
                #pragma unroll
                for (int ni = 0; ni < 4; ni++)
                    mma16816(acc[mi][ni], af[mi], bf[ni]);
        }
        if (t + 2 < nt) issue(kBase + t + 2, (t + 2) % NSTAGE);
    }

    float* Cout = g.C + (size_t)blockIdx.z * g.M * g.ncols;
    const bool useBias = (g.bias != nullptr) && (gz == 1);
    #pragma unroll
    for (int mi = 0; mi < 4; mi++) {
        #pragma unroll
        for (int ni = 0; ni < 4; ni++) {
            int m0 = tileM + mw + mi * 16 + (lane >> 2);
            int n0 = tileN + nw + ni * 8 + (lane & 3) * 2;
            float b0 = 0.f, b1 = 0.f;
            if (useBias) { b0 = g.bias[n0]; b1 = g.bias[n0 + 1]; }
            #pragma unroll
            for (int half = 0; half < 2; half++) {
                int m = m0 + half * 8;
                if (m >= g.M) continue;
                size_t orow;
                if (g.outScatter) {
                    int ob = m / g.rows, on = g.base + m % g.rows;
                    orow = (size_t)ob * NN + on;
                } else {
                    orow = (size_t)m;
                }
                *(float2*)(Cout + orow * g.ncols + n0) =
                    make_float2(acc[mi][ni][half * 2] + b0, acc[mi][ni][half * 2 + 1] + b1);
            }
        }
    }
}

// ================= non-GEMM kernels =================
__global__ void eh_proj_kernel(const float* __restrict__ eh, const float* __restrict__ Wn,
                               const float* __restrict__ Wf, float* __restrict__ en,
                               float* __restrict__ ef) {
    int gw   = (blockIdx.x * blockDim.x + threadIdx.x) >> 5;
    int lane = threadIdx.x & 31;
    if (gw >= 2 * B_ * F_) return;
    int which = (gw >= B_ * F_);
    int rem   = which ? gw - B_ * F_ : gw;
    int b = rem >> 9, f = rem & 511;
    const float4* w4 = (const float4*)((which ? Wf : Wn) + (size_t)f * 1024);
    const float4* e4 = (const float4*)(eh + (size_t)b * 1024);
    float s = 0.f;
    for (int k = lane; k < 256; k += 32) {
        float4 a = w4[k], c = e4[k];
        s += a.x * c.x + a.y * c.y + a.z * c.z + a.w * c.w;
    }
    #pragma unroll
    for (int o = 16; o; o >>= 1) s += __shfl_down_sync(0xffffffffu, s, o);
    if (!lane) (which ? ef : en)[rem] = s;
}

__global__ void dot_kernel(const float* __restrict__ X, const float* __restrict__ v,
                           float* __restrict__ out) {
    int gw   = (blockIdx.x * blockDim.x + threadIdx.x) >> 5;
    int lane = threadIdx.x & 31;
    if (gw >= B_ * NN) return;
    int b = gw / NN;
    const float4* x4 = (const float4*)(X + (size_t)gw * F_);
    const float4* v4 = (const float4*)(v + (size_t)b * F_);
    float s = 0.f;
    #pragma unroll
    for (int k = lane; k < 128; k += 32) {
        float4 a = x4[k], c = v4[k];
        s += a.x * c.x + a.y * c.y + a.z * c.z + a.w * c.w;
    }
    #pragma unroll
    for (int o = 16; o; o >>= 1) s += __shfl_down_sync(0xffffffffu, s, o);
    if (!lane) out[gw] = s;
}

__global__ void feat2s_kernel(const float* __restrict__ feat, const float* __restrict__ en,
                              __nv_bfloat16* __restrict__ o) {
    int bi = blockIdx.x;
    int b = bi / NN, i = bi % NN;
    int cnt = min(i + 3, NN - 1) - i + 1;
    __shared__ float sw[4];
    int t = threadIdx.x;
    int wj = t >> 5, lane = t & 31;
    if (wj < cnt) {
        const float4* x4 = (const float4*)(feat + ((size_t)bi + wj) * F_);
        const float4* v4 = (const float4*)(en + (size_t)b * F_);
        float s = 0.f;
        #pragma unroll
        for (int k = lane; k < 128; k += 32) {
            float4 a = x4[k], c = v4[k];
            s += a.x * c.x + a.y * c.y + a.z * c.z + a.w * c.w;
        }
        #pragma unroll
        for (int off = 16; off; off >>= 1) s += __shfl_down_sync(0xffffffffu, s, off);
        if (!lane) sw[wj] = s;
    }
    __syncthreads();
    float w[4];
    float mx = -1e30f;
    for (int j = 0; j < cnt; j++) { w[j] = sw[j]; mx = fmaxf(mx, w[j]); }
    float ssum = 0.f;
    for (int j = 0; j < cnt; j++) { w[j] = expf(w[j] - mx); ssum += w[j]; }
    float inv = 1.f / ssum;
    const float4* base = (const float4*)(feat + (size_t)bi * F_);
    __nv_bfloat16* orow = o + (size_t)bi * KS;
    {
        int f = t;
        float4 a = make_float4(0.f, 0.f, 0.f, 0.f);
        for (int j = 0; j < cnt; j++) {
            float4 v = base[j * 128 + f];
            a.x += w[j] * v.x; a.y += w[j] * v.y; a.z += w[j] * v.z; a.w += w[j] * v.w;
        }
        a.x *= inv; a.y *= inv; a.z *= inv; a.w *= inv;
        __nv_bfloat16 h0 = __float2bfloat16_rn(a.x), h1 = __float2bfloat16_rn(a.y);
        __nv_bfloat16 h2 = __float2bfloat16_rn(a.z), h3 = __float2bfloat16_rn(a.w);
        orow[f * 4 + 0] = h0; orow[f * 4 + 1] = h1; orow[f * 4 + 2] = h2; orow[f * 4 + 3] = h3;
        orow[512 + f * 4 + 0] = __float2bfloat16_rn(a.x - __bfloat162float(h0));
        orow[512 + f * 4 + 1] = __float2bfloat16_rn(a.y - __bfloat162float(h1));
        orow[512 + f * 4 + 2] = __float2bfloat16_rn(a.z - __bfloat162float(h2));
        orow[512 + f * 4 + 3] = __float2bfloat16_rn(a.w - __bfloat162float(h3));
    }
}

__device__ __forceinline__ void write_split(__nv_bfloat16* p, int f4, float4 hn) {
    __nv_bfloat16 h0 = __float2bfloat16_rn(hn.x), h1 = __float2bfloat16_rn(hn.y);
    __nv_bfloat16 h2 = __float2bfloat16_rn(hn.z), h3 = __float2bfloat16_rn(hn.w);
    p[f4 * 4 + 0] = h0; p[f4 * 4 + 1] = h1; p[f4 * 4 + 2] = h2; p[f4 * 4 + 3] = h3;
    p[512 + f4 * 4 + 0] = __float2bfloat16_rn(hn.x - __bfloat162float(h0));
    p[512 + f4 * 4 + 1] = __float2bfloat16_rn(hn.y - __bfloat162float(h1));
    p[512 + f4 * 4 + 2] = __float2bfloat16_rn(hn.z - __bfloat162float(h2));
    p[512 + f4 * 4 + 3] = __float2bfloat16_rn(hn.w - __bfloat162float(h3));
}

// leaves: nodes 255..510. Writes h, c, hsplit; also pair-sum split for level-1 iou GEMM.
__global__ void leaf_kernel(const float* __restrict__ feiou, float* __restrict__ h,
                            float* __restrict__ c, __nv_bfloat16* __restrict__ hs,
                            __nv_bfloat16* __restrict__ hsum) {
    size_t idx = (size_t)blockIdx.x * blockDim.x + threadIdx.x;   // B_*256*128, exact
    int f4 = (int)(idx & 127);
    size_t t = idx >> 7;
    int j = (int)(t % 256);
    int b = (int)(t / 256);
    size_t row = (size_t)b * NN + 255 + j;
    const float4* r = (const float4*)(feiou + row * NC);
    float4 ig = r[f4], og = r[128 + f4], ug = r[256 + f4];
    float4 cn, hn;
    cn.x = sigm(ig.x) * fmaxf(ug.x, 0.f); hn.x = sigm(og.x) * tanhf(cn.x);
    cn.y = sigm(ig.y) * fmaxf(ug.y, 0.f); hn.y = sigm(og.y) * tanhf(cn.y);
    cn.z = sigm(ig.z) * fmaxf(ug.z, 0.f); hn.z = sigm(og.z) * tanhf(cn.z);
    cn.w = sigm(ig.w) * fmaxf(ug.w, 0.f); hn.w = sigm(og.w) * tanhf(cn.w);
    ((float4*)(c + row * F_))[f4] = cn;
    ((float4*)(h + row * F_))[f4] = hn;
    write_split(hs + row * KS, f4, hn);
    // pair-sum: siblings (j even, j odd) in same block
    __shared__ float4 ex[2][128];
    ex[t & 1][f4] = hn;
    __syncthreads();
    if (!(t & 1)) {
        float4 s = hn; add4(s, ex[1][f4]);
        write_split(hsum + ((size_t)b * 128 + (j >> 1)) * KS, f4, s);
    }
}

// per-level combine: iou from pair-sum GEMM (per-parent), f from per-child GEMM.
__global__ void combine_kernel(const float* __restrict__ lvl_iou, const float* __restrict__ lvl_f,
                               const float* __restrict__ feiou,
                               float* __restrict__ h, float* __restrict__ c,
                               __nv_bfloat16* __restrict__ hs, __nv_bfloat16* __restrict__ hsum,
                               int start, int cnt, int gz, size_t s_iou, size_t s_f) {
    size_t idx = (size_t)blockIdx.x * blockDim.x + threadIdx.x;   // B_*cnt*128, exact
    int f4 = (int)(idx & 127);
    size_t t = idx >> 7;
    int q = (int)(t % cnt);
    int b = (int)(t / cnt);
    int p = start + q;
    size_t prow = (size_t)b * NN + p;
    float4 si = make_float4(0,0,0,0), so = make_float4(0,0,0,0), su = make_float4(0,0,0,0);
    float4 fl = make_float4(0,0,0,0), fr = make_float4(0,0,0,0);
    const float* bi = lvl_iou + ((size_t)b * cnt + q) * 1536;
    const float* bfp = lvl_f + ((size_t)b * 2 * cnt + 2 * q) * 512;
    for (int z = 0; z < gz; z++) {
        const float4* ti = (const float4*)(bi + z * s_iou);
        add4(si, ti[f4]); add4(so, ti[128 + f4]); add4(su, ti[256 + f4]);
        const float4* tf = (const float4*)(bfp + z * s_f);
        add4(fl, tf[f4]); add4(fr, tf[128 + f4]);
    }
    const float4* fi = (const float4*)(feiou + prow * NC);
    float4 ig2 = fi[f4], og2 = fi[128 + f4], ug2 = fi[256 + f4], fe = fi[384 + f4];
    size_t cl = ((size_t)b * NN + 2 * p + 1) * F_;
    float4 cL = ((const float4*)(c + cl))[f4];
    float4 cR = ((const float4*)(c + cl + F_))[f4];
    float4 cn, hn;
    {
        float cs = sigm(fl.x + fe.x) * cL.x + sigm(fr.x + fe.x) * cR.x;
        cn.x = sigm(si.x + ig2.x) * fmaxf(su.x + ug2.x, 0.f) + cs;
        hn.x = sigm(so.x + og2.x) * tanhf(cn.x);
        cs = sigm(fl.y + fe.y) * cL.y + sigm(fr.y + fe.y) * cR.y;
        cn.y = sigm(si.y + ig2.y) * fmaxf(su.y + ug2.y, 0.f) + cs;
        hn.y = sigm(so.y + og2.y) * tanhf(cn.y);
        cs = sigm(fl.z + fe.z) * cL.z + sigm(fr.z + fe.z) * cR.z;
        cn.z = sigm(si.z + ig2.z) * fmaxf(su.z + ug2.z, 0.f) + cs;
        hn.z = sigm(so.z + og2.z) * tanhf(cn.z);
        cs = sigm(fl.w + fe.w) * cL.w + sigm(fr.w + fe.w) * cR.w;
        cn.w = sigm(si.w + ig2.w) * fmaxf(su.w + ug2.w, 0.f) + cs;
        hn.w = sigm(so.w + og2.w) * tanhf(cn.w);
    }
    ((float4*)(c + prow * F_))[f4] = cn;
    ((float4*)(h + prow * F_))[f4] = hn;
    write_split(hs + prow * KS, f4, hn);
    // pair-sum for next level
    __shared__ float4 ex[2][128];
    ex[t & 1][f4] = hn;
    __syncthreads();
    if (cnt > 1 && !(t & 1)) {
        float4 s = hn; add4(s, ex[1][f4]);
        write_split(hsum + ((size_t)b * (cnt >> 1) + (q >> 1)) * KS, f4, s);
    }
}

__global__ void final_kernel(const float* __restrict__ logits, const float* __restrict__ h,
                             float* __restrict__ out) {
    int b = blockIdx.x;
    int t = threadIdx.x;
    __shared__ float sp[512];
    __shared__ float red[17];
    float l = (t < NN) ? logits[b * NN + t] : -1e30f;
    float m = l;
    #pragma unroll
    for (int o = 16; o; o >>= 1) m = fmaxf(m, __shfl_xor_sync(0xffffffffu, m, o));
    if ((t & 31) == 0) red[t >> 5] = m;
    __syncthreads();
    if (t == 0) {
        float mm = red[0];
        for (int i = 1; i < 16; i++) mm = fmaxf(mm, red[i]);
        red[16] = mm;
    }
    __syncthreads();
    float mx = red[16];
    float e = (t < NN) ? expf(l - mx) : 0.f;
    sp[t] = e;
    float s = e;
    #pragma unroll
    for (int o = 16; o; o >>= 1) s += __shfl_xor_sync(0xffffffffu, s, o);
    __syncthreads();
    if ((t & 31) == 0) red[t >> 5] = s;
    __syncthreads();
    if (t == 0) {
        float ss = 0.f;
        for (int i = 0; i < 16; i++) ss += red[i];
        red[16] = 1.f / ss;
    }
    __syncthreads();
    float inv = red[16];
    const float* hb = h + (size_t)b * NN * F_;
    float acc = 0.f;
    for (int i = 0; i < NN; i++) acc += sp[i] * hb[(size_t)i * F_ + t];
    out[b * F_ + t] = acc * inv;
}

// ================= launch =================
extern "C" void kernel_launch(void* const* d_in, const int* in_sizes, int n_in,
                              void* d_out, int out_size) {
    const float* features   = (const float*)d_in[0];
    const float* eh         = (const float*)d_in[5];
    const float* Wn         = (const float*)d_in[6];
    const float* Wf         = (const float*)d_in[7];
    const float* W_U_iou    = (const float*)d_in[8];
    const float* W_U_fe_iou = (const float*)d_in[9];
    const float* b_U_fe_iou = (const float*)d_in[10];
    const float* W_U_f      = (const float*)d_in[11];
    const float* W_U_fe_f   = (const float*)d_in[12];
    const float* b_U_fe_f   = (const float*)d_in[13];
    float* out = (float*)d_out;

    float *p_en, *p_ef, *p_lg, *p_h, *p_c, *p_feiou, *p_lvl, *p_bias;
    __nv_bfloat16 *p_f2s, *p_hs, *p_hsum, *p_wfe, *p_wu;
    cudaGetSymbolAddress((void**)&p_en,    g_enode);
    cudaGetSymbolAddress((void**)&p_ef,    g_eforw);
    cudaGetSymbolAddress((void**)&p_lg,    g_logits);
    cudaGetSymbolAddress((void**)&p_h,     g_h);
    cudaGetSymbolAddress((void**)&p_c,     g_c);
    cudaGetSymbolAddress((void**)&p_feiou, g_feiou);
    cudaGetSymbolAddress((void**)&p_lvl,   g_lvl);
    cudaGetSymbolAddress((void**)&p_bias,  g_biascat);
    cudaGetSymbolAddress((void**)&p_f2s,   g_f2s);
    cudaGetSymbolAddress((void**)&p_hs,    g_hsplit);
    cudaGetSymbolAddress((void**)&p_hsum,  g_hsum);
    cudaGetSymbolAddress((void**)&p_wfe,   g_wfe);
    cudaGetSymbolAddress((void**)&p_wu,    g_wu);
    float* p_lvlf = p_lvl + LVLF_OFF;

    static int smem_set = 0;
    if (!smem_set) {
        cudaFuncSetAttribute(dual_gemm, cudaFuncAttributeMaxDynamicSharedMemorySize, GSMEM);
        smem_set = 1;
    }

    // 0) split all weights + bias
    wsplit_all<<<(2 * NC * 512 + 255) / 256, 256>>>(W_U_fe_iou, W_U_fe_f, W_U_iou, W_U_f,
                                                    p_wfe, p_wu, b_U_fe_iou, b_U_fe_f, p_bias);
    // 1) eh projections + fused attention
    eh_proj_kernel<<<(2 * B_ * F_ * 32 + 255) / 256, 256>>>(eh, Wn, Wf, p_en, p_ef);
    feat2s_kernel<<<B_ * NN, 128>>>(features, p_en, p_f2s);
    // 2) fused fe GEMM: parents [iou|f] (16 N-tiles) + leaves [iou] (12 N-tiles), one launch
    {
        GP gp = { p_f2s, p_wfe, p_bias, p_feiou, B_ * NP, NP, 0, 1, 16, NC };
        GP gl = { p_f2s, p_wfe, p_bias, p_feiou, B_ * 256, 256, 255, 1, 12, NC };
        dim3 grid(28, 64, 1);
        dual_gemm<<<grid, 256, GSMEM>>>(gp, gl);
    }
    // 3) leaves (also writes pair-sum split for level 1)
    leaf_kernel<<<B_ * 256 * 128 / 256, 256>>>(p_feiou, p_h, p_c, p_hs, p_hsum);
    // 4) levels bottom-up: iou GEMM on pair-sums (N=1536) + f GEMM on children (N=512)
    for (int n = 1; n <= 8; n++) {
        int cnt = 1 << (8 - n);
        int start = cnt - 1;
        int Miou = B_ * cnt;
        int Mf   = B_ * 2 * cnt;
        int gz = (Mf <= 2048) ? 3 : 1;
        GP gi = { p_hsum, p_wu, nullptr, p_lvl, Miou, Miou, 0, 0, 12, 1536 };
        GP gf = { p_hs, p_wu + (size_t)1536 * KS, nullptr, p_lvlf,
                  Mf, 2 * cnt, 2 * start + 1, 0, 4, 512 };
        int y = (Mf + 127) / 128;
        dim3 grid(16, y, gz);
        dual_gemm<<<grid, 256, GSMEM>>>(gi, gf);
        combine_kernel<<<B_ * cnt * 128 / 256, 256>>>(p_lvl, p_lvlf, p_feiou, p_h, p_c,
                                                      p_hs, p_hsum, start, cnt, gz,
                                                      (size_t)Miou * 1536, (size_t)Mf * 512);
    }
    // 5) output pooling
    dot_kernel<<<(B_ * NN * 32 + 255) / 256, 256>>>(p_h, p_ef, p_lg);
    final_kernel<<<B_, F_>>>(p_lg, p_h, out);
}

// round 14
// speedup vs baseline: 1.5162x; 1.5162x over previous
#include <cuda_runtime.h>
#include <cuda_bf16.h>
#include <math.h>
#include <stdint.h>

#define B_   32
#define NN   511
#define F_   512
#define NP   255
#define NC   2048   // fe fused output width: [iou(1536) | f(512)]
#define KS   1024   // split activation width: [hi(512) | lo(512)]
#define LVLF_OFF ((size_t)8 * 1024 * 1024)   // float offset of f-region inside g_lvl

// ---------------- scratch (static device memory) ----------------
__device__ __align__(16) float g_enode [B_*F_];
__device__ __align__(16) float g_eforw [B_*F_];
__device__ __align__(16) float g_logits[B_*NN];
__device__ __align__(16) float g_h     [B_*NN*F_];
__device__ __align__(16) float g_c     [B_*NN*F_];
__device__ __align__(16) float g_feiou [(size_t)B_*NN*NC];
__device__ __align__(16) float g_lvl   [(size_t)B_*256*NC];   // iou slices | f slices
__device__ __align__(16) __nv_bfloat16 g_f2s   [(size_t)B_*NN*KS];
__device__ __align__(16) __nv_bfloat16 g_hsplit[(size_t)B_*NN*KS];
__device__ __align__(16) __nv_bfloat16 g_hsum  [(size_t)B_*128*KS];  // pair-sum split
__device__ __align__(16) __nv_bfloat16 g_wfe   [(size_t)NC*KS];
__device__ __align__(16) __nv_bfloat16 g_wu    [(size_t)NC*KS];
__device__ __align__(16) float g_biascat[NC];

__device__ __forceinline__ float sigm(float x) { return 1.f / (1.f + expf(-x)); }
__device__ __forceinline__ uint32_t smem_u32(const void* p) {
    uint32_t a;
    asm("{ .reg .u64 t; cvta.to.shared.u64 t, %1; cvt.u32.u64 %0, t; }" : "=r"(a) : "l"(p));
    return a;
}
#define SWZ(o) ((o) ^ (((o) >> 3) & 0x70))
#define CP16(d, s) asm volatile("cp.async.cg.shared.global [%0], [%1], 16;" :: "r"(d), "l"(s))
#define CP_COMMIT() asm volatile("cp.async.commit_group;")
#define CP_WAIT(n)  asm volatile("cp.async.wait_group %0;" :: "n"(n))

__device__ __forceinline__ void ldmx4(uint32_t* r, uint32_t addr) {
    asm volatile("ldmatrix.sync.aligned.m8n8.x4.shared.b16 {%0,%1,%2,%3}, [%4];"
                 : "=r"(r[0]), "=r"(r[1]), "=r"(r[2]), "=r"(r[3]) : "r"(addr));
}
__device__ __forceinline__ void ldmx2(uint32_t* r, uint32_t addr) {
    asm volatile("ldmatrix.sync.aligned.m8n8.x2.shared.b16 {%0,%1}, [%2];"
                 : "=r"(r[0]), "=r"(r[1]) : "r"(addr));
}
__device__ __forceinline__ void mma16816(float* d, const uint32_t* a, const uint32_t* b) {
    asm volatile("mma.sync.aligned.m16n8k16.row.col.f32.bf16.bf16.f32 "
                 "{%0,%1,%2,%3}, {%4,%5,%6,%7}, {%8,%9}, {%0,%1,%2,%3};"
                 : "+f"(d[0]), "+f"(d[1]), "+f"(d[2]), "+f"(d[3])
                 : "r"(a[0]), "r"(a[1]), "r"(a[2]), "r"(a[3]), "r"(b[0]), "r"(b[1]));
}
__device__ __forceinline__ void add4(float4& a, float4 b) {
    a.x += b.x; a.y += b.y; a.z += b.z; a.w += b.w;
}

// ================= all weights split in ONE launch ================
__global__ void wsplit_all(const float* __restrict__ Wfeiou, const float* __restrict__ Wfef,
                           const float* __restrict__ Wuiou,  const float* __restrict__ Wuf,
                           __nv_bfloat16* __restrict__ Ofe, __nv_bfloat16* __restrict__ Ou,
                           const float* __restrict__ b_iou, const float* __restrict__ b_f,
                           float* __restrict__ bias) {
    int idx = blockIdx.x * blockDim.x + threadIdx.x;
    if (idx < NC) bias[idx] = (idx < 1536) ? b_iou[idx] : b_f[idx - 1536];
    if (idx >= 2 * NC * 512) return;
    int which = idx >= NC * 512;
    int rem = which ? idx - NC * 512 : idx;
    int r = rem >> 9, k = rem & 511;
    const float* W = which ? (r < 1536 ? Wuiou : Wuf) : (r < 1536 ? Wfeiou : Wfef);
    int rl = (r < 1536) ? r : r - 1536;
    float v = W[(size_t)rl * 512 + k];
    __nv_bfloat16 hi = __float2bfloat16_rn(v);
    __nv_bfloat16 lo = __float2bfloat16_rn(v - __bfloat162float(hi));
    __nv_bfloat16* O = which ? Ou : Ofe;
    O[(size_t)r * KS + k]       = hi;
    O[(size_t)r * KS + 512 + k] = lo;
}

// ================= bf16 HMMA dual-GEMM: blockIdx.x range selects GP ===========
// Each field selected into a REGISTER at entry (no reference -> no local-memory spill).
struct GP {
    const __nv_bfloat16* As; const __nv_bfloat16* Wc; const float* bias; float* C;
    int M, rows, base, outScatter, gx, ncols;
};

#define TILE_BYTES 16384
#define NSTAGE 3
#define GSMEM (NSTAGE * 2 * TILE_BYTES + 1024)

__global__ void __launch_bounds__(256) dual_gemm(GP g0, GP g1) {
    extern __shared__ char smem_dyn[];
    const bool first = ((int)blockIdx.x < g0.gx);
    // ---- field-wise register selection (the R13 `const GP&` forced local memory) ----
    const __nv_bfloat16* As = first ? g0.As : g1.As;
    const __nv_bfloat16* Wc = first ? g0.Wc : g1.Wc;
    const float* bias       = first ? g0.bias : g1.bias;
    float* C                = first ? g0.C : g1.C;
    const int M          = first ? g0.M : g1.M;
    const int rows       = first ? g0.rows : g1.rows;
    const int base       = first ? g0.base : g1.base;
    const int outScatter = first ? g0.outScatter : g1.outScatter;
    const int gx         = first ? g0.gx : g1.gx;
    const int ncols      = first ? g0.ncols : g1.ncols;
    const int xo = first ? (int)blockIdx.x : (int)blockIdx.x - g0.gx;
    if (xo >= gx) return;
    const int tileN = xo * 128;
    const int tileM = blockIdx.y * 128;
    if (tileM >= M) return;

    const uint32_t sb0 = smem_u32(smem_dyn);
    const uint32_t ab  = (sb0 + 1023u) & ~1023u;
    const int tid = threadIdx.x;
    const int wid = tid >> 5, lane = tid & 31;
    const int mw = (wid & 1) * 64;
    const int nw = (wid >> 1) * 32;

    const int row  = tid >> 1;
    const int c16b = (tid & 1) * 4;
    int row_g = tileM + row; if (row_g >= M) row_g = M - 1;
    int b = row_g / rows, node = base + row_g % rows;
    const __nv_bfloat16* srcA = As + (size_t)(b * NN + node) * KS;
    const __nv_bfloat16* srcB = Wc + (size_t)(tileN + row) * KS;

    const int gz = gridDim.z;
    const int nt = 24 / gz;
    const int kBase = blockIdx.z * nt;

    auto issue = [&](int c, int buf) {
        const int segsel = c >> 3;
        const int aseg = (segsel == 1) ? 512 : 0;
        const int bseg = (segsel == 2) ? 512 : 0;
        const int kb = (c & 7) * 64;
        const uint32_t sA = ab + buf * 2 * TILE_BYTES;
        const uint32_t sB = sA + TILE_BYTES;
        #pragma unroll
        for (int s = 0; s < 4; s++) {
            int cs = c16b + s;
            int eo = kb + cs * 8;
            CP16(sA + SWZ(row * 128 + cs * 16), srcA + aseg + eo);
            CP16(sB + SWZ(row * 128 + cs * 16), srcB + bseg + eo);
        }
        CP_COMMIT();
    };

    float acc[4][4][4] = {};
    const int a_r = lane & 15, a_q = (lane >> 4) * 16;
    const int b_r = lane & 7,  b_q = ((lane >> 3) & 1) * 16;

    issue(kBase + 0, 0);
    issue(kBase + 1, 1);
    for (int t = 0; t < nt; t++) {
        if (t + 1 < nt) CP_WAIT(1); else CP_WAIT(0);
        __syncthreads();
        const uint32_t sAb = ab + (t % NSTAGE) * 2 * TILE_BYTES;
        const uint32_t sBb = sAb + TILE_BYTES;
        #pragma unroll
        for (int ks = 0; ks < 4; ks++) {
            uint32_t af[4][4], bf[4][2];
            #pragma unroll
            for (int mi = 0; mi < 4; mi++)
                ldmx4(af[mi], sAb + SWZ((mw + mi * 16 + a_r) * 128 + ks * 32 + a_q));
            #pragma unroll
            for (int ni = 0; ni < 4; ni++)
                ldmx2(bf[ni], sBb + SWZ((nw + ni * 8 + b_r) * 128 + ks * 32 + b_q));
            #pragma unroll
            for (int mi = 0; mi < 4; mi++)
                #pragma unroll
                for (int ni = 0; ni < 4; ni++)
                    mma16816(acc[mi][ni], af[mi], bf[ni]);
        }
        if (t + 2 < nt) issue(kBase + t + 2, (t + 2) % NSTAGE);
    }

    float* Cout = C + (size_t)blockIdx.z * M * ncols;
    const bool useBias = (bias != nullptr) && (gz == 1);
    #pragma unroll
    for (int mi = 0; mi < 4; mi++) {
        #pragma unroll
        for (int ni = 0; ni < 4; ni++) {
            int m0 = tileM + mw + mi * 16 + (lane >> 2);
            int n0 = tileN + nw + ni * 8 + (lane & 3) * 2;
            float b0 = 0.f, b1 = 0.f;
            if (useBias) { b0 = bias[n0]; b1 = bias[n0 + 1]; }
            #pragma unroll
            for (int half = 0; half < 2; half++) {
                int m = m0 + half * 8;
                if (m >= M) continue;
                size_t orow;
                if (outScatter) {
                    int ob = m / rows, on = base + m % rows;
                    orow = (size_t)ob * NN + on;
                } else {
                    orow = (size_t)m;
                }
                *(float2*)(Cout + orow * ncols + n0) =
                    make_float2(acc[mi][ni][half * 2] + b0, acc[mi][ni][half * 2 + 1] + b1);
            }
        }
    }
}

// ================= non-GEMM kernels =================
__global__ void eh_proj_kernel(const float* __restrict__ eh, const float* __restrict__ Wn,
                               const float* __restrict__ Wf, float* __restrict__ en,
                               float* __restrict__ ef) {
    int gw   = (blockIdx.x * blockDim.x + threadIdx.x) >> 5;
    int lane = threadIdx.x & 31;
    if (gw >= 2 * B_ * F_) return;
    int which = (gw >= B_ * F_);
    int rem   = which ? gw - B_ * F_ : gw;
    int b = rem >> 9, f = rem & 511;
    const float4* w4 = (const float4*)((which ? Wf : Wn) + (size_t)f * 1024);
    const float4* e4 = (const float4*)(eh + (size_t)b * 1024);
    float s = 0.f;
    for (int k = lane; k < 256; k += 32) {
        float4 a = w4[k], c = e4[k];
        s += a.x * c.x + a.y * c.y + a.z * c.z + a.w * c.w;
    }
    #pragma unroll
    for (int o = 16; o; o >>= 1) s += __shfl_down_sync(0xffffffffu, s, o);
    if (!lane) (which ? ef : en)[rem] = s;
}

__global__ void dot_kernel(const float* __restrict__ X, const float* __restrict__ v,
                           float* __restrict__ out) {
    int gw   = (blockIdx.x * blockDim.x + threadIdx.x) >> 5;
    int lane = threadIdx.x & 31;
    if (gw >= B_ * NN) return;
    int b = gw / NN;
    const float4* x4 = (const float4*)(X + (size_t)gw * F_);
    const float4* v4 = (const float4*)(v + (size_t)b * F_);
    float s = 0.f;
    #pragma unroll
    for (int k = lane; k < 128; k += 32) {
        float4 a = x4[k], c = v4[k];
        s += a.x * c.x + a.y * c.y + a.z * c.z + a.w * c.w;
    }
    #pragma unroll
    for (int o = 16; o; o >>= 1) s += __shfl_down_sync(0xffffffffu, s, o);
    if (!lane) out[gw] = s;
}

__global__ void feat2s_kernel(const float* __restrict__ feat, const float* __restrict__ en,
                              __nv_bfloat16* __restrict__ o) {
    int bi = blockIdx.x;
    int b = bi / NN, i = bi % NN;
    int cnt = min(i + 3, NN - 1) - i + 1;
    __shared__ float sw[4];
    int t = threadIdx.x;
    int wj = t >> 5, lane = t & 31;
    if (wj < cnt) {
        const float4* x4 = (const float4*)(feat + ((size_t)bi + wj) * F_);
        const float4* v4 = (const float4*)(en + (size_t)b * F_);
        float s = 0.f;
        #pragma unroll
        for (int k = lane; k < 128; k += 32) {
            float4 a = x4[k], c = v4[k];
            s += a.x * c.x + a.y * c.y + a.z * c.z + a.w * c.w;
        }
        #pragma unroll
        for (int off = 16; off; off >>= 1) s += __shfl_down_sync(0xffffffffu, s, off);
        if (!lane) sw[wj] = s;
    }
    __syncthreads();
    float w[4];
    float mx = -1e30f;
    for (int j = 0; j < cnt; j++) { w[j] = sw[j]; mx = fmaxf(mx, w[j]); }
    float ssum = 0.f;
    for (int j = 0; j < cnt; j++) { w[j] = expf(w[j] - mx); ssum += w[j]; }
    float inv = 1.f / ssum;
    const float4* base = (const float4*)(feat + (size_t)bi * F_);
    __nv_bfloat16* orow = o + (size_t)bi * KS;
    {
        int f = t;
        float4 a = make_float4(0.f, 0.f, 0.f, 0.f);
        for (int j = 0; j < cnt; j++) {
            float4 v = base[j * 128 + f];
            a.x += w[j] * v.x; a.y += w[j] * v.y; a.z += w[j] * v.z; a.w += w[j] * v.w;
        }
        a.x *= inv; a.y *= inv; a.z *= inv; a.w *= inv;
        __nv_bfloat16 h0 = __float2bfloat16_rn(a.x), h1 = __float2bfloat16_rn(a.y);
        __nv_bfloat16 h2 = __float2bfloat16_rn(a.z), h3 = __float2bfloat16_rn(a.w);
        orow[f * 4 + 0] = h0; orow[f * 4 + 1] = h1; orow[f * 4 + 2] = h2; orow[f * 4 + 3] = h3;
        orow[512 + f * 4 + 0] = __float2bfloat16_rn(a.x - __bfloat162float(h0));
        orow[512 + f * 4 + 1] = __float2bfloat16_rn(a.y - __bfloat162float(h1));
        orow[512 + f * 4 + 2] = __float2bfloat16_rn(a.z - __bfloat162float(h2));
        orow[512 + f * 4 + 3] = __float2bfloat16_rn(a.w - __bfloat162float(h3));
    }
}

__device__ __forceinline__ void write_split(__nv_bfloat16* p, int f4, float4 hn) {
    __nv_bfloat16 h0 = __float2bfloat16_rn(hn.x), h1 = __float2bfloat16_rn(hn.y);
    __nv_bfloat16 h2 = __float2bfloat16_rn(hn.z), h3 = __float2bfloat16_rn(hn.w);
    p[f4 * 4 + 0] = h0; p[f4 * 4 + 1] = h1; p[f4 * 4 + 2] = h2; p[f4 * 4 + 3] = h3;
    p[512 + f4 * 4 + 0] = __float2bfloat16_rn(hn.x - __bfloat162float(h0));
    p[512 + f4 * 4 + 1] = __float2bfloat16_rn(hn.y - __bfloat162float(h1));
    p[512 + f4 * 4 + 2] = __float2bfloat16_rn(hn.z - __bfloat162float(h2));
    p[512 + f4 * 4 + 3] = __float2bfloat16_rn(hn.w - __bfloat162float(h3));
}

// leaves: nodes 255..510. Writes h, c, hsplit; also pair-sum split for level-1 iou GEMM.
__global__ void leaf_kernel(const float* __restrict__ feiou, float* __restrict__ h,
                            float* __restrict__ c, __nv_bfloat16* __restrict__ hs,
                            __nv_bfloat16* __restrict__ hsum) {
    size_t idx = (size_t)blockIdx.x * blockDim.x + threadIdx.x;   // B_*256*128, exact
    int f4 = (int)(idx & 127);
    size_t t = idx >> 7;
    int j = (int)(t % 256);
    int b = (int)(t / 256);
    size_t row = (size_t)b * NN + 255 + j;
    const float4* r = (const float4*)(feiou + row * NC);
    float4 ig = r[f4], og = r[128 + f4], ug = r[256 + f4];
    float4 cn, hn;
    cn.x = sigm(ig.x) * fmaxf(ug.x, 0.f); hn.x = sigm(og.x) * tanhf(cn.x);
    cn.y = sigm(ig.y) * fmaxf(ug.y, 0.f); hn.y = sigm(og.y) * tanhf(cn.y);
    cn.z = sigm(ig.z) * fmaxf(ug.z, 0.f); hn.z = sigm(og.z) * tanhf(cn.z);
    cn.w = sigm(ig.w) * fmaxf(ug.w, 0.f); hn.w = sigm(og.w) * tanhf(cn.w);
    ((float4*)(c + row * F_))[f4] = cn;
    ((float4*)(h + row * F_))[f4] = hn;
    write_split(hs + row * KS, f4, hn);
    __shared__ float4 ex[2][128];
    ex[t & 1][f4] = hn;
    __syncthreads();
    if (!(t & 1)) {
        float4 s = hn; add4(s, ex[1][f4]);
        write_split(hsum + ((size_t)b * 128 + (j >> 1)) * KS, f4, s);
    }
}

// per-level combine: iou from pair-sum GEMM (per-parent), f from per-child GEMM.
__global__ void combine_kernel(const float* __restrict__ lvl_iou, const float* __restrict__ lvl_f,
                               const float* __restrict__ feiou,
                               float* __restrict__ h, float* __restrict__ c,
                               __nv_bfloat16* __restrict__ hs, __nv_bfloat16* __restrict__ hsum,
                               int start, int cnt, int gz, size_t s_iou, size_t s_f) {
    size_t idx = (size_t)blockIdx.x * blockDim.x + threadIdx.x;   // B_*cnt*128, exact
    int f4 = (int)(idx & 127);
    size_t t = idx >> 7;
    int q = (int)(t % cnt);
    int b = (int)(t / cnt);
    int p = start + q;
    size_t prow = (size_t)b * NN + p;
    float4 si = make_float4(0,0,0,0), so = make_float4(0,0,0,0), su = make_float4(0,0,0,0);
    float4 fl = make_float4(0,0,0,0), fr = make_float4(0,0,0,0);
    const float* bi = lvl_iou + ((size_t)b * cnt + q) * 1536;
    const float* bfp = lvl_f + ((size_t)b * 2 * cnt + 2 * q) * 512;
    for (int z = 0; z < gz; z++) {
        const float4* ti = (const float4*)(bi + z * s_iou);
        add4(si, ti[f4]); add4(so, ti[128 + f4]); add4(su, ti[256 + f4]);
        const float4* tf = (const float4*)(bfp + z * s_f);
        add4(fl, tf[f4]); add4(fr, tf[128 + f4]);
    }
    const float4* fi = (const float4*)(feiou + prow * NC);
    float4 ig2 = fi[f4], og2 = fi[128 + f4], ug2 = fi[256 + f4], fe = fi[384 + f4];
    size_t cl = ((size_t)b * NN + 2 * p + 1) * F_;
    float4 cL = ((const float4*)(c + cl))[f4];
    float4 cR = ((const float4*)(c + cl + F_))[f4];
    float4 cn, hn;
    {
        float cs = sigm(fl.x + fe.x) * cL.x + sigm(fr.x + fe.x) * cR.x;
        cn.x = sigm(si.x + ig2.x) * fmaxf(su.x + ug2.x, 0.f) + cs;
        hn.x = sigm(so.x + og2.x) * tanhf(cn.x);
        cs = sigm(fl.y + fe.y) * cL.y + sigm(fr.y + fe.y) * cR.y;
        cn.y = sigm(si.y + ig2.y) * fmaxf(su.y + ug2.y, 0.f) + cs;
        hn.y = sigm(so.y + og2.y) * tanhf(cn.y);
        cs = sigm(fl.z + fe.z) * cL.z + sigm(fr.z + fe.z) * cR.z;
        cn.z = sigm(si.z + ig2.z) * fmaxf(su.z + ug2.z, 0.f) + cs;
        hn.z = sigm(so.z + og2.z) * tanhf(cn.z);
        cs = sigm(fl.w + fe.w) * cL.w + sigm(fr.w + fe.w) * cR.w;
        cn.w = sigm(si.w + ig2.w) * fmaxf(su.w + ug2.w, 0.f) + cs;
        hn.w = sigm(so.w + og2.w) * tanhf(cn.w);
    }
    ((float4*)(c + prow * F_))[f4] = cn;
    ((float4*)(h + prow * F_))[f4] = hn;
    write_split(hs + prow * KS, f4, hn);
    __shared__ float4 ex[2][128];
    ex[t & 1][f4] = hn;
    __syncthreads();
    if (cnt > 1 && !(t & 1)) {
        float4 s = hn; add4(s, ex[1][f4]);
        write_split(hsum + ((size_t)b * (cnt >> 1) + (q >> 1)) * KS, f4, s);
    }
}

__global__ void final_kernel(const float* __restrict__ logits, const float* __restrict__ h,
                             float* __restrict__ out) {
    int b = blockIdx.x;
    int t = threadIdx.x;
    __shared__ float sp[512];
    __shared__ float red[17];
    float l = (t < NN) ? logits[b * NN + t] : -1e30f;
    float m = l;
    #pragma unroll
    for (int o = 16; o; o >>= 1) m = fmaxf(m, __shfl_xor_sync(0xffffffffu, m, o));
    if ((t & 31) == 0) red[t >> 5] = m;
    __syncthreads();
    if (t == 0) {
        float mm = red[0];
        for (int i = 1; i < 16; i++) mm = fmaxf(mm, red[i]);
        red[16] = mm;
    }
    __syncthreads();
    float mx = red[16];
    float e = (t < NN) ? expf(l - mx) : 0.f;
    sp[t] = e;
    float s = e;
    #pragma unroll
    for (int o = 16; o; o >>= 1) s += __shfl_xor_sync(0xffffffffu, s, o);
    __syncthreads();
    if ((t & 31) == 0) red[t >> 5] = s;
    __syncthreads();
    if (t == 0) {
        float ss = 0.f;
        for (int i = 0; i < 16; i++) ss += red[i];
        red[16] = 1.f / ss;
    }
    __syncthreads();
    float inv = red[16];
    const float* hb = h + (size_t)b * NN * F_;
    float acc = 0.f;
    for (int i = 0; i < NN; i++) acc += sp[i] * hb[(size_t)i * F_ + t];
    out[b * F_ + t] = acc * inv;
}

// ================= launch =================
extern "C" void kernel_launch(void* const* d_in, const int* in_sizes, int n_in,
                              void* d_out, int out_size) {
    const float* features   = (const float*)d_in[0];
    const float* eh         = (const float*)d_in[5];
    const float* Wn         = (const float*)d_in[6];
    const float* Wf         = (const float*)d_in[7];
    const float* W_U_iou    = (const float*)d_in[8];
    const float* W_U_fe_iou = (const float*)d_in[9];
    const float* b_U_fe_iou = (const float*)d_in[10];
    const float* W_U_f      = (const float*)d_in[11];
    const float* W_U_fe_f   = (const float*)d_in[12];
    const float* b_U_fe_f   = (const float*)d_in[13];
    float* out = (float*)d_out;

    float *p_en, *p_ef, *p_lg, *p_h, *p_c, *p_feiou, *p_lvl, *p_bias;
    __nv_bfloat16 *p_f2s, *p_hs, *p_hsum, *p_wfe, *p_wu;
    cudaGetSymbolAddress((void**)&p_en,    g_enode);
    cudaGetSymbolAddress((void**)&p_ef,    g_eforw);
    cudaGetSymbolAddress((void**)&p_lg,    g_logits);
    cudaGetSymbolAddress((void**)&p_h,     g_h);
    cudaGetSymbolAddress((void**)&p_c,     g_c);
    cudaGetSymbolAddress((void**)&p_feiou, g_feiou);
    cudaGetSymbolAddress((void**)&p_lvl,   g_lvl);
    cudaGetSymbolAddress((void**)&p_bias,  g_biascat);
    cudaGetSymbolAddress((void**)&p_f2s,   g_f2s);
    cudaGetSymbolAddress((void**)&p_hs,    g_hsplit);
    cudaGetSymbolAddress((void**)&p_hsum,  g_hsum);
    cudaGetSymbolAddress((void**)&p_wfe,   g_wfe);
    cudaGetSymbolAddress((void**)&p_wu,    g_wu);
    float* p_lvlf = p_lvl + LVLF_OFF;

    static int smem_set = 0;
    if (!smem_set) {
        cudaFuncSetAttribute(dual_gemm, cudaFuncAttributeMaxDynamicSharedMemorySize, GSMEM);
        smem_set = 1;
    }

    // 0) split all weights + bias
    wsplit_all<<<(2 * NC * 512 + 255) / 256, 256>>>(W_U_fe_iou, W_U_fe_f, W_U_iou, W_U_f,
                                                    p_wfe, p_wu, b_U_fe_iou, b_U_fe_f, p_bias);
    // 1) eh projections + fused attention
    eh_proj_kernel<<<(2 * B_ * F_ * 32 + 255) / 256, 256>>>(eh, Wn, Wf, p_en, p_ef);
    feat2s_kernel<<<B_ * NN, 128>>>(features, p_en, p_f2s);
    // 2) fused fe GEMM: parents [iou|f] (16 N-tiles) + leaves [iou] (12 N-tiles), one launch
    {
        GP gp = { p_f2s, p_wfe, p_bias, p_feiou, B_ * NP, NP, 0, 1, 16, NC };
        GP gl = { p_f2s, p_wfe, p_bias, p_feiou, B_ * 256, 256, 255, 1, 12, NC };
        dim3 grid(28, 64, 1);
        dual_gemm<<<grid, 256, GSMEM>>>(gp, gl);
    }
    // 3) leaves (also writes pair-sum split for level 1)
    leaf_kernel<<<B_ * 256 * 128 / 256, 256>>>(p_feiou, p_h, p_c, p_hs, p_hsum);
    // 4) levels bottom-up: iou GEMM on pair-sums (N=1536) + f GEMM on children (N=512)
    for (int n = 1; n <= 8; n++) {
        int cnt = 1 << (8 - n);
        int start = cnt - 1;
        int Miou = B_ * cnt;
        int Mf   = B_ * 2 * cnt;
        int gz = (Mf <= 2048) ? 3 : 1;
        GP gi = { p_hsum, p_wu, nullptr, p_lvl, Miou, Miou, 0, 0, 12, 1536 };
        GP gf = { p_hs, p_wu + (size_t)1536 * KS, nullptr, p_lvlf,
                  Mf, 2 * cnt, 2 * start + 1, 0, 4, 512 };
        int y = (Mf + 127) / 128;
        dim3 grid(16, y, gz);
        dual_gemm<<<grid, 256, GSMEM>>>(gi, gf);
        combine_kernel<<<B_ * cnt * 128 / 256, 256>>>(p_lvl, p_lvlf, p_feiou, p_h, p_c,
                                                      p_hs, p_hsum, start, cnt, gz,
                                                      (size_t)Miou * 1536, (size_t)Mf * 512);
    }
    // 5) output pooling
    dot_kernel<<<(B_ * NN * 32 + 255) / 256, 256>>>(p_h, p_ef, p_lg);
    final_kernel<<<B_, F_>>>(p_lg, p_h, out);
}